// round 14
// baseline (speedup 1.0000x reference)
#include <cuda_runtime.h>
#include <cuda_fp16.h>
#include <cstdint>

#define B_ 2
#define T_ 2048
#define C_ 1024
#define H_ 16
#define D_ 64
#define F_ 4096
#define M_ (B_*T_)   // 4096 rows
#define QKVN 3072

// ---------------- scratch (device globals; no runtime allocation) ----------
__device__ __align__(16) __half hb_h  [M_*C_];    // ln1 out (half)
__device__ __align__(16) __half hb_wp [C_*QKVN];  // packed Wqkv (half)
__device__ __align__(16) __half hb_qkv[M_*QKVN];  // qkv activations (half)
__device__ __align__(16) __half hb_att[M_*C_];    // attn out (half)
__device__ __align__(16) __half hb_h2 [M_*C_];    // ln2 out (half)
__device__ __align__(16) __half hb_ff [M_*F_];    // ffn mid (half)
__device__ __align__(16) __half hb_wo [C_*C_];
__device__ __align__(16) __half hb_w1 [C_*F_];
__device__ __align__(16) __half hb_w2 [F_*C_];
__device__ __align__(16) float  g_x1  [M_*C_];    // attn residual out (fp32)

__device__ __forceinline__ uint32_t f2h2(float x, float y) {
    __half2 h = __floats2half2_rn(x, y);
    return *(uint32_t*)&h;
}
__device__ __forceinline__ uint32_t su32(const void* p) {
    return (uint32_t)__cvta_generic_to_shared(p);
}

#define MMA_F16(acc, a, b) \
    asm volatile( \
        "mma.sync.aligned.m16n8k16.row.col.f32.f16.f16.f32 " \
        "{%0,%1,%2,%3},{%4,%5,%6,%7},{%8,%9},{%0,%1,%2,%3};" \
        : "+f"((acc)[0]), "+f"((acc)[1]), "+f"((acc)[2]), "+f"((acc)[3]) \
        : "r"((a)[0]), "r"((a)[1]), "r"((a)[2]), "r"((a)[3]), \
          "r"((b)[0]), "r"((b)[1]))

#define LDSM4(r0, r1, r2, r3, addr) \
    asm volatile("ldmatrix.sync.aligned.m8n8.x4.shared.b16 {%0,%1,%2,%3}, [%4];" \
        : "=r"(r0), "=r"(r1), "=r"(r2), "=r"(r3) : "r"(addr))
#define LDSM4T(r0, r1, r2, r3, addr) \
    asm volatile("ldmatrix.sync.aligned.m8n8.x4.trans.shared.b16 {%0,%1,%2,%3}, [%4];" \
        : "=r"(r0), "=r"(r1), "=r"(r2), "=r"(r3) : "r"(addr))

#define CPA16(dst, src) \
    asm volatile("cp.async.cg.shared.global [%0], [%1], 16;" :: "r"(dst), "l"(src))
#define CPA_COMMIT() asm volatile("cp.async.commit_group;" ::: "memory")
#define CPA_WAIT(n)  asm volatile("cp.async.wait_group %0;" :: "n"(n) : "memory")

// ---------------- LayerNorm: warp-per-row, fp32 in, half out ----------------
__global__ __launch_bounds__(256) void ln_kernel(
    const float* __restrict__ x, const float* __restrict__ g,
    const float* __restrict__ b, __half* __restrict__ out)
{
    int warp = threadIdx.x >> 5, lane = threadIdx.x & 31;
    int row = (blockIdx.x << 3) + warp;
    const float4* xp = (const float4*)(x + (size_t)row * C_);
    float4 v[8];
    float s = 0.f, s2 = 0.f;
    #pragma unroll
    for (int i = 0; i < 8; i++) {
        v[i] = xp[lane + (i << 5)];
        s  += v[i].x + v[i].y + v[i].z + v[i].w;
        s2 += v[i].x*v[i].x + v[i].y*v[i].y + v[i].z*v[i].z + v[i].w*v[i].w;
    }
    #pragma unroll
    for (int o = 16; o; o >>= 1) {
        s  += __shfl_xor_sync(0xffffffffu, s,  o);
        s2 += __shfl_xor_sync(0xffffffffu, s2, o);
    }
    float mean = s * (1.0f/C_);
    float var  = s2 * (1.0f/C_) - mean*mean;
    float rstd = rsqrtf(var + 1e-5f);
    const float4* gp = (const float4*)g;
    const float4* bp = (const float4*)b;
    uint2* op = (uint2*)(out + (size_t)row * C_);
    #pragma unroll
    for (int i = 0; i < 8; i++) {
        float4 gv = gp[lane + (i << 5)];
        float4 bv = bp[lane + (i << 5)];
        uint2 w;
        w.x = f2h2((v[i].x-mean)*rstd*gv.x + bv.x, (v[i].y-mean)*rstd*gv.y + bv.y);
        w.y = f2h2((v[i].z-mean)*rstd*gv.z + bv.z, (v[i].w-mean)*rstd*gv.w + bv.w);
        op[lane + (i << 5)] = w;
    }
}

// ---------------- merged weight prep: Wo/W1/W2 fp32 -> fp16 ------------------
__global__ __launch_bounds__(256) void wprep_kernel(
    const float* __restrict__ Wo, const float* __restrict__ W1,
    const float* __restrict__ W2, __half* __restrict__ woh,
    __half* __restrict__ w1h, __half* __restrict__ w2h)
{
    size_t i = ((size_t)blockIdx.x*256 + threadIdx.x) << 2;
    const float* src; __half* dst; size_t off;
    const size_t S0 = (size_t)C_*C_, S1 = S0 + (size_t)C_*F_;
    if (i < S0)      { src = Wo; dst = woh; off = i; }
    else if (i < S1) { src = W1; dst = w1h; off = i - S0; }
    else             { src = W2; dst = w2h; off = i - S1; }
    float4 v = *(const float4*)(src + off);
    uint2 w;
    w.x = f2h2(v.x, v.y); w.y = f2h2(v.z, v.w);
    *(uint2*)(dst + off) = w;
}

// ---------------- repack Wq/Wk/Wv [H][C][D] -> half [C][3*C] ----------------
__global__ __launch_bounds__(256) void repack_kernel(
    const float* __restrict__ Wq, const float* __restrict__ Wk,
    const float* __restrict__ Wv, __half* __restrict__ Wp)
{
    int idx = blockIdx.x*256 + threadIdx.x;        // over C*C
    int which = blockIdx.y;
    const float* W = (which==0) ? Wq : (which==1) ? Wk : Wv;
    int c = idx >> 10, n = idx & 1023;
    int h = n >> 6, d = n & 63;
    Wp[(size_t)c*QKVN + which*C_ + n] = __float2half_rn(W[((size_t)h*C_ + c)*D_ + d]);
}

// ---- fp16 GEMM: 128x128 tile, 256 thr, warp 32x64, 4-stage, 2 CTAs/SM -----
#define GSTAGE 18944
#define GBOF   10240
#define GT_SMEM (4*GSTAGE)    // 75776 B per CTA

template<int RELU, int HASRES, int HASBIAS, int OUTHALF>
__global__ __launch_bounds__(256, 2) void tgemm(
    const __half* __restrict__ A, const __half* __restrict__ Bm,
    void* __restrict__ Cm, int M, int N, int K,
    const float* __restrict__ bias, const float* __restrict__ res)
{
    extern __shared__ char dsm[];
    int tid = threadIdx.x;
    int m0 = blockIdx.y << 7, n0 = blockIdx.x << 7;
    int warp = tid >> 5, lane = tid & 31;
    int l16 = lane & 15, l2 = lane >> 4;
    int gid = lane >> 2, tig = lane & 3;
    int wm = (warp & 3) << 5;        // 4 m-strips of 32 rows
    int wn = (warp >> 2) << 6;       // 2 n-strips of 64 cols

    float acc[2][8][4] = {};

    // cp.async maps (256 threads)
    int ra = tid >> 1, ca = (tid & 1) << 4;    // A: row 0..127, 16-half col base
    int rb = tid >> 3, nb = (tid & 7) << 4;    // B: k-row 0..31, 16-half col base
    const __half* Ap = A  + (size_t)(m0 + ra) * K + ca;
    const __half* Bp = Bm + (size_t)rb * N + n0 + nb;
    uint32_t aoff = (uint32_t)((ra*40 + ca)*2);
    uint32_t boff = (uint32_t)(GBOF + (rb*136 + nb)*2);
    uint32_t sbase = su32(dsm);

    int KT = K >> 5;
    // prologue: tiles 0,1
    #pragma unroll
    for (int p = 0; p < 2; p++) {
        const __half* ap = Ap + (p<<5);
        const __half* bp = Bp + (size_t)(p<<5) * N;
        uint32_t sb = sbase + p*GSTAGE;
        CPA16(sb + aoff,      ap);
        CPA16(sb + aoff + 16, ap + 8);
        CPA16(sb + boff,      bp);
        CPA16(sb + boff + 16, bp + 8);
        CPA_COMMIT();
    }

    for (int kt = 0; kt < KT; kt++) {
        if (kt + 2 < KT) {
            int t = kt + 2;
            const __half* ap = Ap + (t<<5);
            const __half* bp = Bp + (size_t)(t<<5) * N;
            uint32_t sb = sbase + (t & 3)*GSTAGE;
            CPA16(sb + aoff,      ap);
            CPA16(sb + aoff + 16, ap + 8);
            CPA16(sb + boff,      bp);
            CPA16(sb + boff + 16, bp + 8);
            CPA_COMMIT();
            CPA_WAIT(2);
        } else if (kt + 1 < KT) {
            CPA_WAIT(1);
        } else {
            CPA_WAIT(0);
        }
        __syncthreads();

        const __half* Ah = (const __half*)(dsm + (kt & 3)*GSTAGE);
        const __half* Bh = (const __half*)(dsm + (kt & 3)*GSTAGE + GBOF);
        #pragma unroll
        for (int ks = 0; ks < 2; ks++) {
            unsigned a[2][4], bfr[8][2];
            #pragma unroll
            for (int mt = 0; mt < 2; mt++) {
                uint32_t ad = su32(Ah + (wm + (mt<<4) + l16)*40 + (ks<<4) + (l2<<3));
                LDSM4(a[mt][0], a[mt][1], a[mt][2], a[mt][3], ad);
            }
            #pragma unroll
            for (int np = 0; np < 4; np++) {
                uint32_t bd = su32(Bh + ((ks<<4) + l16)*136 + wn + (np<<4) + (l2<<3));
                uint32_t r0, r1, r2, r3;
                LDSM4T(r0, r1, r2, r3, bd);
                bfr[2*np][0] = r0; bfr[2*np][1] = r1;
                bfr[2*np+1][0] = r2; bfr[2*np+1][1] = r3;
            }
            #pragma unroll
            for (int mt = 0; mt < 2; mt++)
                #pragma unroll
                for (int nt = 0; nt < 8; nt++)
                    MMA_F16(acc[mt][nt], a[mt], bfr[nt]);
        }
    }

    #pragma unroll
    for (int mt = 0; mt < 2; mt++) {
        int mr = m0 + wm + (mt<<4) + gid;
        #pragma unroll
        for (int nt = 0; nt < 8; nt++) {
            int nc = n0 + wn + (nt<<3) + (tig<<1);
            float2 bb = make_float2(0.f, 0.f);
            if (HASBIAS) bb = *(const float2*)(bias + nc);
            float2 o0 = make_float2(acc[mt][nt][0] + bb.x, acc[mt][nt][1] + bb.y);
            float2 o1 = make_float2(acc[mt][nt][2] + bb.x, acc[mt][nt][3] + bb.y);
            if (RELU) {
                o0.x = fmaxf(o0.x, 0.f); o0.y = fmaxf(o0.y, 0.f);
                o1.x = fmaxf(o1.x, 0.f); o1.y = fmaxf(o1.y, 0.f);
            }
            if (HASRES) {
                float2 r0 = *(const float2*)(res + (size_t)mr * N + nc);
                float2 r1 = *(const float2*)(res + (size_t)(mr+8) * N + nc);
                o0.x += r0.x; o0.y += r0.y;
                o1.x += r1.x; o1.y += r1.y;
            }
            if (OUTHALF) {
                __half* Ch = (__half*)Cm;
                *(uint32_t*)(Ch + (size_t)mr     * N + nc) = f2h2(o0.x, o0.y);
                *(uint32_t*)(Ch + (size_t)(mr+8) * N + nc) = f2h2(o1.x, o1.y);
            } else {
                float* Cf = (float*)Cm;
                *(float2*)(Cf + (size_t)mr     * N + nc) = o0;
                *(float2*)(Cf + (size_t)(mr+8) * N + nc) = o1;
            }
        }
    }
}

// ---------------- fp16 flash attention, register softmax, 4-stage K/V ring --
#define ASTG   18432
#define AVOF   9216
#define ATT_SMEM_BYTES (4*ASTG)

__global__ __launch_bounds__(256, 2) void attn_kernel(
    const __half* __restrict__ qkv, __half* __restrict__ out)
{
    extern __shared__ char asmem[];
    int qt = (int)gridDim.x - 1 - (int)blockIdx.x;   // heavy tiles first
    int bh = blockIdx.y;
    int q0 = qt << 7;
    int bb = bh >> 4, hh = bh & 15;
    const __half* Qg = qkv + (size_t)(bb * T_) * QKVN + hh * D_;
    const __half* Kg = Qg + C_;
    const __half* Vg = Qg + 2*C_;
    int tid = threadIdx.x;
    int warp = tid >> 5, lane = tid & 31;
    int l16 = lane & 15, l2 = lane >> 4;
    int gid = lane >> 2, tig = lane & 3;
    int i0 = warp << 4;

    int cr = tid >> 2, cc = (tid & 3) << 4;
    uint32_t kdst[4], vdst[4];
    #pragma unroll
    for (int s = 0; s < 4; s++) {
        kdst[s] = su32(asmem + s*ASTG        + (cr*72 + cc)*2);
        vdst[s] = su32(asmem + s*ASTG + AVOF + (cr*72 + cc)*2);
    }

    unsigned qa[4][4];
    {
        const __half* q0p = Qg + (size_t)(q0 + i0 + gid) * QKVN;
        const __half* q1p = q0p + 8 * QKVN;
        const __half2 sc = __half2half2(__float2half(0.03125f));
        #pragma unroll
        for (int ks = 0; ks < 4; ks++) {
            int c = (ks<<4) + (tig<<1);
            __half2 w0 = __hmul2(*(const __half2*)(q0p + c),     sc);
            __half2 w1 = __hmul2(*(const __half2*)(q1p + c),     sc);
            __half2 w2 = __hmul2(*(const __half2*)(q0p + c + 8), sc);
            __half2 w3 = __hmul2(*(const __half2*)(q1p + c + 8), sc);
            qa[ks][0] = *(uint32_t*)&w0; qa[ks][1] = *(uint32_t*)&w1;
            qa[ks][2] = *(uint32_t*)&w2; qa[ks][3] = *(uint32_t*)&w3;
        }
    }

    float oacc[8][4] = {};
    float m0 = -1e30f, m1 = -1e30f, l0 = 0.f, l1 = 0.f;
    int r0g = q0 + i0 + gid, r1g = r0g + 8;

    int ktmax = 2*qt + 1;
    #pragma unroll
    for (int p = 0; p < 2; p++) {
        const __half* kp = Kg + (size_t)((p<<6) + cr) * QKVN + cc;
        const __half* vp = Vg + (size_t)((p<<6) + cr) * QKVN + cc;
        CPA16(kdst[p], kp); CPA16(kdst[p] + 16, kp + 8);
        CPA16(vdst[p], vp); CPA16(vdst[p] + 16, vp + 8);
        CPA_COMMIT();
    }

    for (int kt = 0; kt <= ktmax; kt++) {
        int st = kt & 3;
        int k0 = kt << 6;
        if (kt + 2 <= ktmax) {
            int s = (kt + 2) & 3;
            const __half* kp = Kg + (size_t)(((kt+2)<<6) + cr) * QKVN + cc;
            const __half* vp = Vg + (size_t)(((kt+2)<<6) + cr) * QKVN + cc;
            CPA16(kdst[s], kp); CPA16(kdst[s] + 16, kp + 8);
            CPA16(vdst[s], vp); CPA16(vdst[s] + 16, vp + 8);
            CPA_COMMIT();
            CPA_WAIT(2);
        } else if (kt + 1 <= ktmax) {
            CPA_WAIT(1);
        } else {
            CPA_WAIT(0);
        }
        __syncthreads();

        const __half* Kh = (const __half*)(asmem + st*ASTG);
        const __half* Vh = (const __half*)(asmem + st*ASTG + AVOF);

        float sacc[8][4] = {};
        #pragma unroll
        for (int ks = 0; ks < 4; ks++) {
            #pragma unroll
            for (int np = 0; np < 4; np++) {
                uint32_t kd = su32(Kh + ((np<<4) + l16)*72 + (ks<<4) + (l2<<3));
                uint32_t t0, t1, t2, t3;
                LDSM4(t0, t1, t2, t3, kd);
                unsigned b0[2] = {t0, t2}, b1[2] = {t1, t3};
                MMA_F16(sacc[2*np],   qa[ks], b0);
                MMA_F16(sacc[2*np+1], qa[ks], b1);
            }
        }

        if (kt >= 2*qt) {
            #pragma unroll
            for (int nt = 0; nt < 8; nt++) {
                int jb = k0 + (nt<<3) + (tig<<1);
                if (jb     > r0g) sacc[nt][0] = -1e30f;
                if (jb + 1 > r0g) sacc[nt][1] = -1e30f;
                if (jb     > r1g) sacc[nt][2] = -1e30f;
                if (jb + 1 > r1g) sacc[nt][3] = -1e30f;
            }
        }

        {
            float mx0 = -1e30f, mx1 = -1e30f;
            #pragma unroll
            for (int nt = 0; nt < 8; nt++) {
                mx0 = fmaxf(mx0, fmaxf(sacc[nt][0], sacc[nt][1]));
                mx1 = fmaxf(mx1, fmaxf(sacc[nt][2], sacc[nt][3]));
            }
            mx0 = fmaxf(mx0, __shfl_xor_sync(0xffffffffu, mx0, 1));
            mx0 = fmaxf(mx0, __shfl_xor_sync(0xffffffffu, mx0, 2));
            mx1 = fmaxf(mx1, __shfl_xor_sync(0xffffffffu, mx1, 1));
            mx1 = fmaxf(mx1, __shfl_xor_sync(0xffffffffu, mx1, 2));
            float m0n = fmaxf(m0, mx0), m1n = fmaxf(m1, mx1);
            float al0 = __expf(m0 - m0n), al1 = __expf(m1 - m1n);
            float s0 = 0.f, s1 = 0.f;
            #pragma unroll
            for (int nt = 0; nt < 8; nt++) {
                sacc[nt][0] = __expf(sacc[nt][0] - m0n);
                sacc[nt][1] = __expf(sacc[nt][1] - m0n);
                sacc[nt][2] = __expf(sacc[nt][2] - m1n);
                sacc[nt][3] = __expf(sacc[nt][3] - m1n);
                s0 += sacc[nt][0] + sacc[nt][1];
                s1 += sacc[nt][2] + sacc[nt][3];
            }
            s0 += __shfl_xor_sync(0xffffffffu, s0, 1);
            s0 += __shfl_xor_sync(0xffffffffu, s0, 2);
            s1 += __shfl_xor_sync(0xffffffffu, s1, 1);
            s1 += __shfl_xor_sync(0xffffffffu, s1, 2);
            l0 = l0 * al0 + s0;  m0 = m0n;
            l1 = l1 * al1 + s1;  m1 = m1n;
            #pragma unroll
            for (int nt = 0; nt < 8; nt++) {
                oacc[nt][0] *= al0; oacc[nt][1] *= al0;
                oacc[nt][2] *= al1; oacc[nt][3] *= al1;
            }
        }

        #pragma unroll
        for (int ks = 0; ks < 4; ks++) {
            unsigned a[4];
            a[0] = f2h2(sacc[2*ks  ][0], sacc[2*ks  ][1]);
            a[1] = f2h2(sacc[2*ks  ][2], sacc[2*ks  ][3]);
            a[2] = f2h2(sacc[2*ks+1][0], sacc[2*ks+1][1]);
            a[3] = f2h2(sacc[2*ks+1][2], sacc[2*ks+1][3]);
            #pragma unroll
            for (int np = 0; np < 4; np++) {
                uint32_t vdx = su32(Vh + ((ks<<4) + l16)*72 + (np<<4) + (l2<<3));
                uint32_t t0, t1, t2, t3;
                LDSM4T(t0, t1, t2, t3, vdx);
                unsigned b0[2] = {t0, t1}, b1[2] = {t2, t3};
                MMA_F16(oacc[2*np],   a, b0);
                MMA_F16(oacc[2*np+1], a, b1);
            }
        }
    }

    {
        float inv0 = 1.0f / l0;
        float inv1 = 1.0f / l1;
        __half* o0 = out + ((size_t)(bb * T_ + r0g)) * C_ + hh * D_ + (tig<<1);
        __half* o1 = o0 + 8 * C_;
        #pragma unroll
        for (int nt = 0; nt < 8; nt++) {
            *(uint32_t*)(o0 + (nt<<3)) = f2h2(oacc[nt][0]*inv0, oacc[nt][1]*inv0);
            *(uint32_t*)(o1 + (nt<<3)) = f2h2(oacc[nt][2]*inv1, oacc[nt][3]*inv1);
        }
    }
}

// ---------------- launch ----------------------------------------------------
extern "C" void kernel_launch(void* const* d_in, const int* in_sizes, int n_in,
                              void* d_out, int out_size)
{
    const float* x   = (const float*)d_in[0];
    const float* Wq  = (const float*)d_in[1];
    const float* Wk  = (const float*)d_in[2];
    const float* Wv  = (const float*)d_in[3];
    const float* Wo  = (const float*)d_in[4];
    const float* bo  = (const float*)d_in[5];
    const float* W1  = (const float*)d_in[6];
    const float* b1  = (const float*)d_in[7];
    const float* W2  = (const float*)d_in[8];
    const float* b2  = (const float*)d_in[9];
    const float* g1  = (const float*)d_in[10];
    const float* be1 = (const float*)d_in[11];
    const float* g2  = (const float*)d_in[12];
    const float* be2 = (const float*)d_in[13];
    float* out = (float*)d_out;

    __half *h, *wp, *qkv, *att, *h2, *ff, *woh, *w1h, *w2h;
    float *x1;
    cudaGetSymbolAddress((void**)&h,   hb_h);
    cudaGetSymbolAddress((void**)&wp,  hb_wp);
    cudaGetSymbolAddress((void**)&qkv, hb_qkv);
    cudaGetSymbolAddress((void**)&att, hb_att);
    cudaGetSymbolAddress((void**)&h2,  hb_h2);
    cudaGetSymbolAddress((void**)&ff,  hb_ff);
    cudaGetSymbolAddress((void**)&woh, hb_wo);
    cudaGetSymbolAddress((void**)&w1h, hb_w1);
    cudaGetSymbolAddress((void**)&w2h, hb_w2);
    cudaGetSymbolAddress((void**)&x1,  g_x1);

    cudaFuncSetAttribute(attn_kernel,
        cudaFuncAttributeMaxDynamicSharedMemorySize, ATT_SMEM_BYTES);
    cudaFuncSetAttribute(tgemm<0,0,0,1>,
        cudaFuncAttributeMaxDynamicSharedMemorySize, GT_SMEM);
    cudaFuncSetAttribute(tgemm<0,1,1,0>,
        cudaFuncAttributeMaxDynamicSharedMemorySize, GT_SMEM);
    cudaFuncSetAttribute(tgemm<1,0,1,1>,
        cudaFuncAttributeMaxDynamicSharedMemorySize, GT_SMEM);

    // ---- fork weight-prep onto a side stream (captured via event fork) ----
    cudaStream_t s2;
    cudaStreamCreateWithFlags(&s2, cudaStreamNonBlocking);
    cudaEvent_t e0, eR, eW;
    cudaEventCreateWithFlags(&e0, cudaEventDisableTiming);
    cudaEventCreateWithFlags(&eR, cudaEventDisableTiming);
    cudaEventCreateWithFlags(&eW, cudaEventDisableTiming);

    cudaEventRecord(e0, 0);               // fork point on capture stream
    cudaStreamWaitEvent(s2, e0, 0);
    repack_kernel<<<dim3((C_*C_)/256, 3), 256, 0, s2>>>(Wq, Wk, Wv, wp);
    cudaEventRecord(eR, s2);              // repack done (needed by QKV)
    wprep_kernel<<<(C_*C_ + 2*C_*F_)/1024, 256, 0, s2>>>(Wo, W1, W2, woh, w1h, w2h);
    cudaEventRecord(eW, s2);              // wprep done (needed by Wo GEMM)

    // 1) LN1 (half out) — overlaps repack
    ln_kernel<<<M_/8, 256>>>(x, g1, be1, h);
    // 2) join repack, then QKV projection
    cudaStreamWaitEvent(0, eR, 0);
    tgemm<0,0,0,1><<<dim3(QKVN/128, M_/128), 256, GT_SMEM>>>(h, wp, qkv, M_, QKVN, C_, nullptr, nullptr);
    // 3) causal flash attention (register softmax, 4-stage K/V ring)
    attn_kernel<<<dim3(T_/128, B_*H_), 256, ATT_SMEM_BYTES>>>(qkv, att);
    // 4) join wprep, then Wo projection + bias + residual (fp32 out)
    cudaStreamWaitEvent(0, eW, 0);
    tgemm<0,1,1,0><<<dim3(C_/128, M_/128), 256, GT_SMEM>>>(att, woh, x1, M_, C_, C_, bo, x);
    // 5) LN2 (half out)
    ln_kernel<<<M_/8, 256>>>(x1, g2, be2, h2);
    // 6) FFN up + ReLU (half out)
    tgemm<1,0,1,1><<<dim3(F_/128, M_/128), 256, GT_SMEM>>>(h2, w1h, ff, M_, F_, C_, b1, nullptr);
    // 7) FFN down + bias + residual -> final fp32 output
    tgemm<0,1,1,0><<<dim3(C_/128, M_/128), 256, GT_SMEM>>>(ff, w2h, out, M_, C_, F_, b2, x1);
}

// round 15
// speedup vs baseline: 1.0658x; 1.0658x over previous
#include <cuda_runtime.h>
#include <cuda_fp16.h>
#include <cstdint>

#define B_ 2
#define T_ 2048
#define C_ 1024
#define H_ 16
#define D_ 64
#define F_ 4096
#define M_ (B_*T_)   // 4096 rows
#define QKVN 3072

// ---------------- scratch (device globals; no runtime allocation) ----------
__device__ __align__(16) __half hb_h  [M_*C_];    // ln1 out (half)
__device__ __align__(16) __half hb_wp [C_*QKVN];  // packed Wqkv (half)
__device__ __align__(16) __half hb_qkv[M_*QKVN];  // qkv activations (half)
__device__ __align__(16) __half hb_att[M_*C_];    // attn out (half)
__device__ __align__(16) __half hb_h2 [M_*C_];    // ln2 out (half)
__device__ __align__(16) __half hb_ff [M_*F_];    // ffn mid (half)
__device__ __align__(16) __half hb_wo [C_*C_];
__device__ __align__(16) __half hb_w1 [C_*F_];
__device__ __align__(16) __half hb_w2 [F_*C_];
__device__ __align__(16) float  g_x1  [M_*C_];    // attn residual out (fp32)

__device__ __forceinline__ uint32_t f2h2(float x, float y) {
    __half2 h = __floats2half2_rn(x, y);
    return *(uint32_t*)&h;
}
__device__ __forceinline__ uint32_t su32(const void* p) {
    return (uint32_t)__cvta_generic_to_shared(p);
}

#define MMA_F16(acc, a, b) \
    asm volatile( \
        "mma.sync.aligned.m16n8k16.row.col.f32.f16.f16.f32 " \
        "{%0,%1,%2,%3},{%4,%5,%6,%7},{%8,%9},{%0,%1,%2,%3};" \
        : "+f"((acc)[0]), "+f"((acc)[1]), "+f"((acc)[2]), "+f"((acc)[3]) \
        : "r"((a)[0]), "r"((a)[1]), "r"((a)[2]), "r"((a)[3]), \
          "r"((b)[0]), "r"((b)[1]))

#define LDSM4(r0, r1, r2, r3, addr) \
    asm volatile("ldmatrix.sync.aligned.m8n8.x4.shared.b16 {%0,%1,%2,%3}, [%4];" \
        : "=r"(r0), "=r"(r1), "=r"(r2), "=r"(r3) : "r"(addr))
#define LDSM4T(r0, r1, r2, r3, addr) \
    asm volatile("ldmatrix.sync.aligned.m8n8.x4.trans.shared.b16 {%0,%1,%2,%3}, [%4];" \
        : "=r"(r0), "=r"(r1), "=r"(r2), "=r"(r3) : "r"(addr))

#define CPA16(dst, src) \
    asm volatile("cp.async.cg.shared.global [%0], [%1], 16;" :: "r"(dst), "l"(src))
#define CPA_COMMIT() asm volatile("cp.async.commit_group;" ::: "memory")
#define CPA_WAIT(n)  asm volatile("cp.async.wait_group %0;" :: "n"(n) : "memory")

// ---------------- LayerNorm: warp-per-row, fp32 in, half out ----------------
__global__ __launch_bounds__(256) void ln_kernel(
    const float* __restrict__ x, const float* __restrict__ g,
    const float* __restrict__ b, __half* __restrict__ out)
{
    int warp = threadIdx.x >> 5, lane = threadIdx.x & 31;
    int row = (blockIdx.x << 3) + warp;
    const float4* xp = (const float4*)(x + (size_t)row * C_);
    float4 v[8];
    float s = 0.f, s2 = 0.f;
    #pragma unroll
    for (int i = 0; i < 8; i++) {
        v[i] = xp[lane + (i << 5)];
        s  += v[i].x + v[i].y + v[i].z + v[i].w;
        s2 += v[i].x*v[i].x + v[i].y*v[i].y + v[i].z*v[i].z + v[i].w*v[i].w;
    }
    #pragma unroll
    for (int o = 16; o; o >>= 1) {
        s  += __shfl_xor_sync(0xffffffffu, s,  o);
        s2 += __shfl_xor_sync(0xffffffffu, s2, o);
    }
    float mean = s * (1.0f/C_);
    float var  = s2 * (1.0f/C_) - mean*mean;
    float rstd = rsqrtf(var + 1e-5f);
    const float4* gp = (const float4*)g;
    const float4* bp = (const float4*)b;
    uint2* op = (uint2*)(out + (size_t)row * C_);
    #pragma unroll
    for (int i = 0; i < 8; i++) {
        float4 gv = gp[lane + (i << 5)];
        float4 bv = bp[lane + (i << 5)];
        uint2 w;
        w.x = f2h2((v[i].x-mean)*rstd*gv.x + bv.x, (v[i].y-mean)*rstd*gv.y + bv.y);
        w.y = f2h2((v[i].z-mean)*rstd*gv.z + bv.z, (v[i].w-mean)*rstd*gv.w + bv.w);
        op[lane + (i << 5)] = w;
    }
}

// ---------------- merged weight prep: Wo/W1/W2 fp32 -> fp16 ------------------
__global__ __launch_bounds__(256) void wprep_kernel(
    const float* __restrict__ Wo, const float* __restrict__ W1,
    const float* __restrict__ W2, __half* __restrict__ woh,
    __half* __restrict__ w1h, __half* __restrict__ w2h)
{
    size_t i = ((size_t)blockIdx.x*256 + threadIdx.x) << 2;
    const float* src; __half* dst; size_t off;
    const size_t S0 = (size_t)C_*C_, S1 = S0 + (size_t)C_*F_;
    if (i < S0)      { src = Wo; dst = woh; off = i; }
    else if (i < S1) { src = W1; dst = w1h; off = i - S0; }
    else             { src = W2; dst = w2h; off = i - S1; }
    float4 v = *(const float4*)(src + off);
    uint2 w;
    w.x = f2h2(v.x, v.y); w.y = f2h2(v.z, v.w);
    *(uint2*)(dst + off) = w;
}

// ---------------- repack Wq/Wk/Wv [H][C][D] -> half [C][3*C] ----------------
__global__ __launch_bounds__(256) void repack_kernel(
    const float* __restrict__ Wq, const float* __restrict__ Wk,
    const float* __restrict__ Wv, __half* __restrict__ Wp)
{
    int idx = blockIdx.x*256 + threadIdx.x;        // over C*C
    int which = blockIdx.y;
    const float* W = (which==0) ? Wq : (which==1) ? Wk : Wv;
    int c = idx >> 10, n = idx & 1023;
    int h = n >> 6, d = n & 63;
    Wp[(size_t)c*QKVN + which*C_ + n] = __float2half_rn(W[((size_t)h*C_ + c)*D_ + d]);
}

// ---------------- fp16 GEMM: 128x256 tile, 512 thr (16 warps), 8-stage ring -
#define GSTAGE 27136
#define GBOF   10240
#define GT_SMEM (8*GSTAGE)    // 217088 B

template<int RELU, int HASRES, int HASBIAS, int OUTHALF>
__global__ __launch_bounds__(512, 1) void tgemm(
    const __half* __restrict__ A, const __half* __restrict__ Bm,
    void* __restrict__ Cm, int M, int N, int K,
    const float* __restrict__ bias, const float* __restrict__ res)
{
    extern __shared__ char dsm[];
    int tid = threadIdx.x;
    int m0 = blockIdx.y << 7, n0 = blockIdx.x << 8;
    int warp = tid >> 5, lane = tid & 31;
    int l16 = lane & 15, l2 = lane >> 4;
    int gid = lane >> 2, tig = lane & 3;
    int wm = (warp & 3) << 5;        // 4 m-strips of 32 rows
    int wn = (warp >> 2) << 6;       // 4 n-strips of 64 cols

    float acc[2][8][4] = {};

    // cp.async maps (512 threads)
    int ra = tid >> 2, ca = (tid & 3) << 3;    // A: row 0..127, 8-half col base
    int rb = tid >> 4, nb = (tid & 15) << 4;   // B: k-row 0..31, 16-half col base
    const __half* Ap = A  + (size_t)(m0 + ra) * K + ca;
    const __half* Bp = Bm + (size_t)rb * N + n0 + nb;
    uint32_t aoff = (uint32_t)((ra*40 + ca)*2);
    uint32_t boff = (uint32_t)(GBOF + (rb*264 + nb)*2);
    uint32_t sbase = su32(dsm);

    int KT = K >> 5;
    int NB = KT >> 1;
    // prologue: tiles 0..3
    #pragma unroll
    for (int p = 0; p < 4; p++) {
        const __half* ap = Ap + (p<<5);
        const __half* bp = Bp + (size_t)(p<<5) * N;
        uint32_t sb = sbase + p*GSTAGE;
        CPA16(sb + aoff, ap);
        CPA16(sb + boff,      bp);
        CPA16(sb + boff + 16, bp + 8);
        CPA_COMMIT();
    }

    for (int b = 0; b < NB; b++) {
        int t0 = b << 1;
        if (b + 2 < NB) {
            #pragma unroll
            for (int q = 0; q < 2; q++) {
                int t = t0 + 4 + q;
                const __half* ap = Ap + (t<<5);
                const __half* bp = Bp + (size_t)(t<<5) * N;
                uint32_t sb = sbase + (t & 7)*GSTAGE;
                CPA16(sb + aoff, ap);
                CPA16(sb + boff,      bp);
                CPA16(sb + boff + 16, bp + 8);
                CPA_COMMIT();
            }
            CPA_WAIT(4);
        } else if (b + 1 < NB) {
            CPA_WAIT(2);
        } else {
            CPA_WAIT(0);
        }
        __syncthreads();

        // compute tiles t0, t0+1
        #pragma unroll
        for (int q = 0; q < 2; q++) {
            const __half* Ah = (const __half*)(dsm + ((t0 + q) & 7)*GSTAGE);
            const __half* Bh = (const __half*)(dsm + ((t0 + q) & 7)*GSTAGE + GBOF);
            #pragma unroll
            for (int ks = 0; ks < 2; ks++) {
                unsigned a[2][4], bfr[8][2];
                #pragma unroll
                for (int mt = 0; mt < 2; mt++) {
                    uint32_t ad = su32(Ah + (wm + (mt<<4) + l16)*40 + (ks<<4) + (l2<<3));
                    LDSM4(a[mt][0], a[mt][1], a[mt][2], a[mt][3], ad);
                }
                #pragma unroll
                for (int np = 0; np < 4; np++) {
                    uint32_t bd = su32(Bh + ((ks<<4) + l16)*264 + wn + (np<<4) + (l2<<3));
                    uint32_t r0, r1, r2, r3;
                    LDSM4T(r0, r1, r2, r3, bd);
                    bfr[2*np][0] = r0; bfr[2*np][1] = r1;
                    bfr[2*np+1][0] = r2; bfr[2*np+1][1] = r3;
                }
                #pragma unroll
                for (int mt = 0; mt < 2; mt++)
                    #pragma unroll
                    for (int nt = 0; nt < 8; nt++)
                        MMA_F16(acc[mt][nt], a[mt], bfr[nt]);
            }
        }
    }

    #pragma unroll
    for (int mt = 0; mt < 2; mt++) {
        int mr = m0 + wm + (mt<<4) + gid;
        #pragma unroll
        for (int nt = 0; nt < 8; nt++) {
            int nc = n0 + wn + (nt<<3) + (tig<<1);
            float2 bb = make_float2(0.f, 0.f);
            if (HASBIAS) bb = *(const float2*)(bias + nc);
            float2 o0 = make_float2(acc[mt][nt][0] + bb.x, acc[mt][nt][1] + bb.y);
            float2 o1 = make_float2(acc[mt][nt][2] + bb.x, acc[mt][nt][3] + bb.y);
            if (RELU) {
                o0.x = fmaxf(o0.x, 0.f); o0.y = fmaxf(o0.y, 0.f);
                o1.x = fmaxf(o1.x, 0.f); o1.y = fmaxf(o1.y, 0.f);
            }
            if (HASRES) {
                float2 r0 = *(const float2*)(res + (size_t)mr * N + nc);
                float2 r1 = *(const float2*)(res + (size_t)(mr+8) * N + nc);
                o0.x += r0.x; o0.y += r0.y;
                o1.x += r1.x; o1.y += r1.y;
            }
            if (OUTHALF) {
                __half* Ch = (__half*)Cm;
                *(uint32_t*)(Ch + (size_t)mr     * N + nc) = f2h2(o0.x, o0.y);
                *(uint32_t*)(Ch + (size_t)(mr+8) * N + nc) = f2h2(o1.x, o1.y);
            } else {
                float* Cf = (float*)Cm;
                *(float2*)(Cf + (size_t)mr     * N + nc) = o0;
                *(float2*)(Cf + (size_t)(mr+8) * N + nc) = o1;
            }
        }
    }
}

// ---------------- fp16 flash attention, register softmax, 4-stage K/V ring --
#define ASTG   18432
#define AVOF   9216
#define ATT_SMEM_BYTES (4*ASTG)

__global__ __launch_bounds__(256, 2) void attn_kernel(
    const __half* __restrict__ qkv, __half* __restrict__ out)
{
    extern __shared__ char asmem[];
    int qt = (int)gridDim.x - 1 - (int)blockIdx.x;   // heavy tiles first
    int bh = blockIdx.y;
    int q0 = qt << 7;
    int bb = bh >> 4, hh = bh & 15;
    const __half* Qg = qkv + (size_t)(bb * T_) * QKVN + hh * D_;
    const __half* Kg = Qg + C_;
    const __half* Vg = Qg + 2*C_;
    int tid = threadIdx.x;
    int warp = tid >> 5, lane = tid & 31;
    int l16 = lane & 15, l2 = lane >> 4;
    int gid = lane >> 2, tig = lane & 3;
    int i0 = warp << 4;

    int cr = tid >> 2, cc = (tid & 3) << 4;
    uint32_t kdst[4], vdst[4];
    #pragma unroll
    for (int s = 0; s < 4; s++) {
        kdst[s] = su32(asmem + s*ASTG        + (cr*72 + cc)*2);
        vdst[s] = su32(asmem + s*ASTG + AVOF + (cr*72 + cc)*2);
    }

    unsigned qa[4][4];
    {
        const __half* q0p = Qg + (size_t)(q0 + i0 + gid) * QKVN;
        const __half* q1p = q0p + 8 * QKVN;
        const __half2 sc = __half2half2(__float2half(0.03125f));
        #pragma unroll
        for (int ks = 0; ks < 4; ks++) {
            int c = (ks<<4) + (tig<<1);
            __half2 w0 = __hmul2(*(const __half2*)(q0p + c),     sc);
            __half2 w1 = __hmul2(*(const __half2*)(q1p + c),     sc);
            __half2 w2 = __hmul2(*(const __half2*)(q0p + c + 8), sc);
            __half2 w3 = __hmul2(*(const __half2*)(q1p + c + 8), sc);
            qa[ks][0] = *(uint32_t*)&w0; qa[ks][1] = *(uint32_t*)&w1;
            qa[ks][2] = *(uint32_t*)&w2; qa[ks][3] = *(uint32_t*)&w3;
        }
    }

    float oacc[8][4] = {};
    float m0 = -1e30f, m1 = -1e30f, l0 = 0.f, l1 = 0.f;
    int r0g = q0 + i0 + gid, r1g = r0g + 8;

    int ktmax = 2*qt + 1;
    #pragma unroll
    for (int p = 0; p < 2; p++) {
        const __half* kp = Kg + (size_t)((p<<6) + cr) * QKVN + cc;
        const __half* vp = Vg + (size_t)((p<<6) + cr) * QKVN + cc;
        CPA16(kdst[p], kp); CPA16(kdst[p] + 16, kp + 8);
        CPA16(vdst[p], vp); CPA16(vdst[p] + 16, vp + 8);
        CPA_COMMIT();
    }

    for (int kt = 0; kt <= ktmax; kt++) {
        int st = kt & 3;
        int k0 = kt << 6;
        if (kt + 2 <= ktmax) {
            int s = (kt + 2) & 3;
            const __half* kp = Kg + (size_t)(((kt+2)<<6) + cr) * QKVN + cc;
            const __half* vp = Vg + (size_t)(((kt+2)<<6) + cr) * QKVN + cc;
            CPA16(kdst[s], kp); CPA16(kdst[s] + 16, kp + 8);
            CPA16(vdst[s], vp); CPA16(vdst[s] + 16, vp + 8);
            CPA_COMMIT();
            CPA_WAIT(2);
        } else if (kt + 1 <= ktmax) {
            CPA_WAIT(1);
        } else {
            CPA_WAIT(0);
        }
        __syncthreads();

        const __half* Kh = (const __half*)(asmem + st*ASTG);
        const __half* Vh = (const __half*)(asmem + st*ASTG + AVOF);

        float sacc[8][4] = {};
        #pragma unroll
        for (int ks = 0; ks < 4; ks++) {
            #pragma unroll
            for (int np = 0; np < 4; np++) {
                uint32_t kd = su32(Kh + ((np<<4) + l16)*72 + (ks<<4) + (l2<<3));
                uint32_t t0, t1, t2, t3;
                LDSM4(t0, t1, t2, t3, kd);
                unsigned b0[2] = {t0, t2}, b1[2] = {t1, t3};
                MMA_F16(sacc[2*np],   qa[ks], b0);
                MMA_F16(sacc[2*np+1], qa[ks], b1);
            }
        }

        if (kt >= 2*qt) {
            #pragma unroll
            for (int nt = 0; nt < 8; nt++) {
                int jb = k0 + (nt<<3) + (tig<<1);
                if (jb     > r0g) sacc[nt][0] = -1e30f;
                if (jb + 1 > r0g) sacc[nt][1] = -1e30f;
                if (jb     > r1g) sacc[nt][2] = -1e30f;
                if (jb + 1 > r1g) sacc[nt][3] = -1e30f;
            }
        }

        {
            float mx0 = -1e30f, mx1 = -1e30f;
            #pragma unroll
            for (int nt = 0; nt < 8; nt++) {
                mx0 = fmaxf(mx0, fmaxf(sacc[nt][0], sacc[nt][1]));
                mx1 = fmaxf(mx1, fmaxf(sacc[nt][2], sacc[nt][3]));
            }
            mx0 = fmaxf(mx0, __shfl_xor_sync(0xffffffffu, mx0, 1));
            mx0 = fmaxf(mx0, __shfl_xor_sync(0xffffffffu, mx0, 2));
            mx1 = fmaxf(mx1, __shfl_xor_sync(0xffffffffu, mx1, 1));
            mx1 = fmaxf(mx1, __shfl_xor_sync(0xffffffffu, mx1, 2));
            float m0n = fmaxf(m0, mx0), m1n = fmaxf(m1, mx1);
            float al0 = __expf(m0 - m0n), al1 = __expf(m1 - m1n);
            float s0 = 0.f, s1 = 0.f;
            #pragma unroll
            for (int nt = 0; nt < 8; nt++) {
                sacc[nt][0] = __expf(sacc[nt][0] - m0n);
                sacc[nt][1] = __expf(sacc[nt][1] - m0n);
                sacc[nt][2] = __expf(sacc[nt][2] - m1n);
                sacc[nt][3] = __expf(sacc[nt][3] - m1n);
                s0 += sacc[nt][0] + sacc[nt][1];
                s1 += sacc[nt][2] + sacc[nt][3];
            }
            s0 += __shfl_xor_sync(0xffffffffu, s0, 1);
            s0 += __shfl_xor_sync(0xffffffffu, s0, 2);
            s1 += __shfl_xor_sync(0xffffffffu, s1, 1);
            s1 += __shfl_xor_sync(0xffffffffu, s1, 2);
            l0 = l0 * al0 + s0;  m0 = m0n;
            l1 = l1 * al1 + s1;  m1 = m1n;
            #pragma unroll
            for (int nt = 0; nt < 8; nt++) {
                oacc[nt][0] *= al0; oacc[nt][1] *= al0;
                oacc[nt][2] *= al1; oacc[nt][3] *= al1;
            }
        }

        #pragma unroll
        for (int ks = 0; ks < 4; ks++) {
            unsigned a[4];
            a[0] = f2h2(sacc[2*ks  ][0], sacc[2*ks  ][1]);
            a[1] = f2h2(sacc[2*ks  ][2], sacc[2*ks  ][3]);
            a[2] = f2h2(sacc[2*ks+1][0], sacc[2*ks+1][1]);
            a[3] = f2h2(sacc[2*ks+1][2], sacc[2*ks+1][3]);
            #pragma unroll
            for (int np = 0; np < 4; np++) {
                uint32_t vdx = su32(Vh + ((ks<<4) + l16)*72 + (np<<4) + (l2<<3));
                uint32_t t0, t1, t2, t3;
                LDSM4T(t0, t1, t2, t3, vdx);
                unsigned b0[2] = {t0, t1}, b1[2] = {t2, t3};
                MMA_F16(oacc[2*np],   a, b0);
                MMA_F16(oacc[2*np+1], a, b1);
            }
        }
    }

    {
        float inv0 = 1.0f / l0;
        float inv1 = 1.0f / l1;
        __half* o0 = out + ((size_t)(bb * T_ + r0g)) * C_ + hh * D_ + (tig<<1);
        __half* o1 = o0 + 8 * C_;
        #pragma unroll
        for (int nt = 0; nt < 8; nt++) {
            *(uint32_t*)(o0 + (nt<<3)) = f2h2(oacc[nt][0]*inv0, oacc[nt][1]*inv0);
            *(uint32_t*)(o1 + (nt<<3)) = f2h2(oacc[nt][2]*inv1, oacc[nt][3]*inv1);
        }
    }
}

// ---------------- launch ----------------------------------------------------
extern "C" void kernel_launch(void* const* d_in, const int* in_sizes, int n_in,
                              void* d_out, int out_size)
{
    const float* x   = (const float*)d_in[0];
    const float* Wq  = (const float*)d_in[1];
    const float* Wk  = (const float*)d_in[2];
    const float* Wv  = (const float*)d_in[3];
    const float* Wo  = (const float*)d_in[4];
    const float* bo  = (const float*)d_in[5];
    const float* W1  = (const float*)d_in[6];
    const float* b1  = (const float*)d_in[7];
    const float* W2  = (const float*)d_in[8];
    const float* b2  = (const float*)d_in[9];
    const float* g1  = (const float*)d_in[10];
    const float* be1 = (const float*)d_in[11];
    const float* g2  = (const float*)d_in[12];
    const float* be2 = (const float*)d_in[13];
    float* out = (float*)d_out;

    __half *h, *wp, *qkv, *att, *h2, *ff, *woh, *w1h, *w2h;
    float *x1;
    cudaGetSymbolAddress((void**)&h,   hb_h);
    cudaGetSymbolAddress((void**)&wp,  hb_wp);
    cudaGetSymbolAddress((void**)&qkv, hb_qkv);
    cudaGetSymbolAddress((void**)&att, hb_att);
    cudaGetSymbolAddress((void**)&h2,  hb_h2);
    cudaGetSymbolAddress((void**)&ff,  hb_ff);
    cudaGetSymbolAddress((void**)&woh, hb_wo);
    cudaGetSymbolAddress((void**)&w1h, hb_w1);
    cudaGetSymbolAddress((void**)&w2h, hb_w2);
    cudaGetSymbolAddress((void**)&x1,  g_x1);

    cudaFuncSetAttribute(attn_kernel,
        cudaFuncAttributeMaxDynamicSharedMemorySize, ATT_SMEM_BYTES);
    cudaFuncSetAttribute(tgemm<0,0,0,1>,
        cudaFuncAttributeMaxDynamicSharedMemorySize, GT_SMEM);
    cudaFuncSetAttribute(tgemm<0,1,1,0>,
        cudaFuncAttributeMaxDynamicSharedMemorySize, GT_SMEM);
    cudaFuncSetAttribute(tgemm<1,0,1,1>,
        cudaFuncAttributeMaxDynamicSharedMemorySize, GT_SMEM);

    // ---- fork weight-prep onto a side stream (captured via event fork) ----
    cudaStream_t s2;
    cudaStreamCreateWithFlags(&s2, cudaStreamNonBlocking);
    cudaEvent_t e0, eR, eW;
    cudaEventCreateWithFlags(&e0, cudaEventDisableTiming);
    cudaEventCreateWithFlags(&eR, cudaEventDisableTiming);
    cudaEventCreateWithFlags(&eW, cudaEventDisableTiming);

    cudaEventRecord(e0, 0);               // fork point on capture stream
    cudaStreamWaitEvent(s2, e0, 0);
    repack_kernel<<<dim3((C_*C_)/256, 3), 256, 0, s2>>>(Wq, Wk, Wv, wp);
    cudaEventRecord(eR, s2);              // repack done (needed by QKV)
    wprep_kernel<<<(C_*C_ + 2*C_*F_)/1024, 256, 0, s2>>>(Wo, W1, W2, woh, w1h, w2h);
    cudaEventRecord(eW, s2);              // wprep done (needed by Wo GEMM)

    // 1) LN1 (half out) — overlaps repack
    ln_kernel<<<M_/8, 256>>>(x, g1, be1, h);
    // 2) join repack, then QKV projection (wprep continues in background)
    cudaStreamWaitEvent(0, eR, 0);
    tgemm<0,0,0,1><<<dim3(QKVN/256, M_/128), 512, GT_SMEM>>>(h, wp, qkv, M_, QKVN, C_, nullptr, nullptr);
    // 3) causal flash attention (register softmax, 4-stage K/V ring)
    attn_kernel<<<dim3(T_/128, B_*H_), 256, ATT_SMEM_BYTES>>>(qkv, att);
    // 4) join wprep, then Wo projection + bias + residual (fp32 out)
    cudaStreamWaitEvent(0, eW, 0);
    tgemm<0,1,1,0><<<dim3(C_/256, M_/128), 512, GT_SMEM>>>(att, woh, x1, M_, C_, C_, bo, x);
    // 5) LN2 (half out)
    ln_kernel<<<M_/8, 256>>>(x1, g2, be2, h2);
    // 6) FFN up + ReLU (half out)
    tgemm<1,0,1,1><<<dim3(F_/256, M_/128), 512, GT_SMEM>>>(h2, w1h, ff, M_, F_, C_, b1, nullptr);
    // 7) FFN down + bias + residual -> final fp32 output
    tgemm<0,1,1,0><<<dim3(C_/256, M_/128), 512, GT_SMEM>>>(ff, w2h, out, M_, C_, F_, b2, x1);
}